// round 6
// baseline (speedup 1.0000x reference)
#include <cuda_runtime.h>
#include <cuda_bf16.h>

// ROI bilinear pooling (tf.image.resize half-pixel-center semantics, per ROI).
// img:  (1, 64, 64, 1024) float32, NHWC
// rois: (1, R, 4) int32  [x, y, w, h]
// out:  (1, R, 7, 7, 1024) float32
//
// R5: one CTA per output row (r, py), 256 threads x float4 channels.
// Vertical blend hoisted per distinct column; previous pixel's two blended
// columns carried in registers and reused when x-coords repeat (CTA-uniform
// conditions -> no divergence). Cuts L1 gather wavefronts ~35%.

#define POOL 7
#define HW   64
#define C    1024
#define C4   (C / 4)

__global__ __launch_bounds__(256) void roi_pool_row_kernel(
    const float* __restrict__ img,
    const int*   __restrict__ rois,
    float*       __restrict__ out)
{
    const int row = blockIdx.x;          // r*7 + py
    const int r   = row / POOL;
    const int py  = row - r * POOL;

    // ROI box [x, y, w, h] (broadcast load)
    const int4 roi = __ldg(((const int4*)rois) + r);
    const int bx = roi.x, by = roi.y, bw = roi.z, bh = roi.w;

    // ---- vertical coords: once per CTA ----
    const float sy = (py + 0.5f) * ((float)bh / (float)POOL) - 0.5f;
    const float fy = floorf(sy);
    const float ty = sy - fy;
    const int   iy = (int)fy;
    const int   y0 = by + min(max(iy,     0), bh - 1);
    const int   y1 = by + min(max(iy + 1, 0), bh - 1);
    const float wty0 = 1.0f - ty;

    const float4* row0 = ((const float4*)img) + (size_t)y0 * (HW * C4);
    const float4* row1 = ((const float4*)img) + (size_t)y1 * (HW * C4);

    const int c = threadIdx.x;           // channel slice 0..255
    float4* outp = ((float4*)out) + (size_t)row * (POOL * C4) + c;

    const float xscale = (float)bw / (float)POOL;
    const int   xmax   = bw - 1;

    // Carried pair: last pixel's (x0, v(x0)) and (x1, v(x1)).
    int    xA = -0x40000000, xB = -0x40000000;
    float4 vA, vB;

#pragma unroll
    for (int px = 0; px < POOL; px++) {
        // ---- horizontal coords for this px (CTA-uniform) ----
        const float sx = (px + 0.5f) * xscale - 0.5f;
        const float fx = floorf(sx);
        const float tx = sx - fx;
        const int   ix = (int)fx;
        const int   x0 = bx + min(max(ix,     0), xmax);
        const int   x1 = bx + min(max(ix + 1, 0), xmax);

        float4 v0, v1;

        // v0 = vertically blended column x0 (reuse if carried)
        if (x0 == xB) {
            v0 = vB;
        } else if (x0 == xA) {
            v0 = vA;
        } else {
            const float4 a = __ldg(row0 + x0 * C4 + c);
            const float4 g = __ldg(row1 + x0 * C4 + c);
            v0.x = a.x * wty0 + g.x * ty;
            v0.y = a.y * wty0 + g.y * ty;
            v0.z = a.z * wty0 + g.z * ty;
            v0.w = a.w * wty0 + g.w * ty;
        }

        // v1 = vertically blended column x1 (reuse if duplicate or carried)
        if (x1 == x0) {
            v1 = v0;
        } else if (x1 == xB) {
            v1 = vB;
        } else {
            const float4 b = __ldg(row0 + x1 * C4 + c);
            const float4 d = __ldg(row1 + x1 * C4 + c);
            v1.x = b.x * wty0 + d.x * ty;
            v1.y = b.y * wty0 + d.y * ty;
            v1.z = b.z * wty0 + d.z * ty;
            v1.w = b.w * wty0 + d.w * ty;
        }

        // horizontal blend
        const float wtx0 = 1.0f - tx;
        float4 o;
        o.x = v0.x * wtx0 + v1.x * tx;
        o.y = v0.y * wtx0 + v1.y * tx;
        o.z = v0.z * wtx0 + v1.z * tx;
        o.w = v0.w * wtx0 + v1.w * tx;

        outp[px * C4] = o;

        xA = x0; vA = v0;
        xB = x1; vB = v1;
    }
}

extern "C" void kernel_launch(void* const* d_in, const int* in_sizes, int n_in,
                              void* d_out, int out_size)
{
    const float* img  = (const float*)d_in[0];
    const int*   rois = (const int*)d_in[1];
    float*       out  = (float*)d_out;

    const int R = in_sizes[1] / 4;       // number of ROIs
    const int blocks = R * POOL;         // one CTA per output row

    roi_pool_row_kernel<<<blocks, 256>>>(img, rois, out);
}